// round 3
// baseline (speedup 1.0000x reference)
#include <cuda_runtime.h>

#define NN 50000         // n_node
#define KP 8             // k_path
#define LP 6             // l_path
#define DN 64            // d_node
#define DP 128           // d_path
#define NE 1600000       // n_edge
#define PROJ_COLS 640    // (LP-1) * DP

// Scratch: projected features, proj[node][l*128 + d] = sum_c W[d, l*64+c] * feat[node, c]
// Row NN (=50000) is the zero-pad row.
__device__ float g_proj[(size_t)(NN + 1) * PROJ_COLS];

// Index dtype flag: 1 if paths/edge_ids are int64, 0 if int32. Set by detect kernel.
__device__ int g_is64;

#define FMA_F32X2(d, a, b, c) \
  asm("fma.rn.f32x2 %0, %1, %2, %3;" : "=l"(d) : "l"(a), "l"(b), "l"(c))

// ---------------------------------------------------------------------------
// Dtype sniff: int64 index data with values in [0, 50001) has all-zero high
// words; int32 randint data essentially never has 32 consecutive zero odd words.
// ---------------------------------------------------------------------------
__global__ void detect_dtype(const unsigned int* __restrict__ paths_raw) {
  int all_hi_zero = 1;
  for (int i = 1; i < 64; i += 2)
    if (paths_raw[i] != 0u) { all_hi_zero = 0; break; }
  g_is64 = all_hi_zero;
}

// ---------------------------------------------------------------------------
// Phase 1: proj = feat @ W^T (per-l blocks).  M=50001, N=640, K=64.
// ---------------------------------------------------------------------------
__global__ void __launch_bounds__(256, 2) phase1_proj(
    const float* __restrict__ feat, const float* __restrict__ W) {
  __shared__ float As[64 * 68];   // [m][k], stride 68 floats
  __shared__ float Bs[64 * 64];   // [d][k], XOR-swizzled 16B chunks

  const int t = threadIdx.x;
  const int node0 = blockIdx.x * 64;
  const int cb = blockIdx.y;       // 0..9
  const int l = cb >> 1;           // path position 0..4
  const int dbase = (cb & 1) * 64;

  {
    const int c4 = (t & 15) * 4;
    const int rbase = t >> 4;
#pragma unroll
    for (int r = 0; r < 4; r++) {
      int m = rbase + r * 16;
      int node = node0 + m;
      float4 v = make_float4(0.f, 0.f, 0.f, 0.f);
      if (node < NN)
        v = *(const float4*)(feat + (size_t)node * DN + c4);
      *(float4*)(As + m * 68 + c4) = v;
    }
    const int c4i = t & 15;
#pragma unroll
    for (int r = 0; r < 4; r++) {
      int dl = rbase + r * 16;
      float4 v = *(const float4*)(W + (size_t)(dbase + dl) * 320 + l * 64 + c4i * 4);
      int sw = c4i ^ (dl >> 2);
      *(float4*)(Bs + dl * 64 + sw * 4) = v;
    }
  }
  __syncthreads();

  const int tx = t & 15;
  const int ty = t >> 4;

  unsigned long long acc0[4][4], acc1[4][4];
#pragma unroll
  for (int i = 0; i < 4; i++)
#pragma unroll
    for (int j = 0; j < 4; j++) { acc0[i][j] = 0ull; acc1[i][j] = 0ull; }

#pragma unroll
  for (int kc = 0; kc < 16; kc++) {
    ulonglong2 a[4], b[4];
#pragma unroll
    for (int mi = 0; mi < 4; mi++)
      a[mi] = *(const ulonglong2*)(As + (ty * 4 + mi) * 68 + kc * 4);
#pragma unroll
    for (int ni = 0; ni < 4; ni++) {
      int dl = tx * 4 + ni;
      int sw = kc ^ tx;
      b[ni] = *(const ulonglong2*)(Bs + dl * 64 + sw * 4);
    }
#pragma unroll
    for (int mi = 0; mi < 4; mi++)
#pragma unroll
      for (int ni = 0; ni < 4; ni++) {
        FMA_F32X2(acc0[mi][ni], a[mi].x, b[ni].x, acc0[mi][ni]);
        FMA_F32X2(acc1[mi][ni], a[mi].y, b[ni].y, acc1[mi][ni]);
      }
  }

#pragma unroll
  for (int mi = 0; mi < 4; mi++) {
    int node = node0 + ty * 4 + mi;
    if (node <= NN) {
      float4 o;
      float* po = (float*)&o;
#pragma unroll
      for (int ni = 0; ni < 4; ni++) {
        unsigned lo0, hi0, lo1, hi1;
        asm("mov.b64 {%0,%1}, %2;" : "=r"(lo0), "=r"(hi0) : "l"(acc0[mi][ni]));
        asm("mov.b64 {%0,%1}, %2;" : "=r"(lo1), "=r"(hi1) : "l"(acc1[mi][ni]));
        po[ni] = (__uint_as_float(lo0) + __uint_as_float(hi0)) +
                 (__uint_as_float(lo1) + __uint_as_float(hi1));
      }
      *(float4*)(g_proj + (size_t)node * PROJ_COLS + l * DP + dbase + tx * 4) = o;
    }
  }
}

// ---------------------------------------------------------------------------
// Phase 2: one warp per (n,k). Index buffers read per the sniffed dtype.
// ---------------------------------------------------------------------------
__global__ void __launch_bounds__(256) phase2_gather(
    const void* __restrict__ paths_v,
    const void* __restrict__ eids_v,
    const float* __restrict__ weight,
    float* __restrict__ out) {
  const long long gw = (((long long)blockIdx.x * blockDim.x) + threadIdx.x) >> 5;
  const int lane = threadIdx.x & 31;
  if (gw >= (long long)NN * KP) return;

  const int is64 = g_is64;

  long long idx[LP];
  float w[LP - 1];
  if (is64) {
    const long long* p = (const long long*)paths_v + gw * LP;
    const long long* e = (const long long*)eids_v + gw * (LP - 1);
#pragma unroll
    for (int i = 0; i < LP; i++) {
      long long v = p[i];
      idx[i] = v < 0 ? 0 : (v > NN ? NN : v);
    }
#pragma unroll
    for (int i = 0; i < LP - 1; i++) {
      long long ev = e[i];
      ev = ev < 0 ? 0 : (ev > NE - 1 ? NE - 1 : ev);
      w[i] = weight[ev];
    }
  } else {
    const int* p = (const int*)paths_v + gw * LP;
    const int* e = (const int*)eids_v + gw * (LP - 1);
#pragma unroll
    for (int i = 0; i < LP; i++) {
      int v = p[i];
      idx[i] = v < 0 ? 0 : (v > NN ? NN : v);
    }
#pragma unroll
    for (int i = 0; i < LP - 1; i++) {
      int ev = e[i];
      ev = ev < 0 ? 0 : (ev > NE - 1 ? NE - 1 : ev);
      w[i] = weight[ev];
    }
  }

  const int col = lane * 4;
  float4 va[LP - 1], vb[LP - 1];
#pragma unroll
  for (int i = 0; i < LP - 1; i++) {
    va[i] = *(const float4*)(g_proj + (size_t)idx[i] * PROJ_COLS + i * DP + col);
    vb[i] = *(const float4*)(g_proj + (size_t)idx[i + 1] * PROJ_COLS + i * DP + col);
  }

  float4 acc = make_float4(0.f, 0.f, 0.f, 0.f);
#pragma unroll
  for (int i = 0; i < LP - 1; i++) {
    acc.x += va[i].x + w[i] * vb[i].x;
    acc.y += va[i].y + w[i] * vb[i].y;
    acc.z += va[i].z + w[i] * vb[i].z;
    acc.w += va[i].w + w[i] * vb[i].w;
  }
  *(float4*)(out + gw * DP + col) = acc;
}

// ---------------------------------------------------------------------------
// Launch. Inputs identified BY ELEMENT COUNT (all five distinct):
//   feat=3,200,000 f32 | weight=1,600,000 f32 | W=40,960 f32
//   paths=2,400,000 (i32 or i64) | edge_ids=2,000,000 (i32 or i64)
// ---------------------------------------------------------------------------
extern "C" void kernel_launch(void* const* d_in, const int* in_sizes, int n_in,
                              void* d_out, int out_size) {
  const float* feat = 0;
  const float* weight = 0;
  const float* W = 0;
  const void* paths = 0;
  const void* eids = 0;

  for (int i = 0; i < n_in; i++) {
    switch (in_sizes[i]) {
      case 3200000: feat   = (const float*)d_in[i]; break;
      case 1600000: weight = (const float*)d_in[i]; break;
      case 40960:   W      = (const float*)d_in[i]; break;
      case 2400000: paths  = d_in[i];               break;
      case 2000000: eids   = d_in[i];               break;
      default: break;
    }
  }
  if (!feat || !weight || !W || !paths || !eids) return;

  float* out = (float*)d_out;

  detect_dtype<<<1, 1>>>((const unsigned int*)paths);

  dim3 g1((NN + 1 + 63) / 64, 10);
  phase1_proj<<<g1, 256>>>(feat, W);

  long long warps = (long long)NN * KP;               // 400,000
  int blocks = (int)((warps * 32 + 255) / 256);       // 50,000
  phase2_gather<<<blocks, 256>>>(paths, eids, weight, out);
}

// round 4
// speedup vs baseline: 1.4175x; 1.4175x over previous
#include <cuda_runtime.h>
#include <cuda_fp16.h>

#define NN 50000         // n_node
#define KP 8             // k_path
#define LP 6             // l_path
#define DN 64            // d_node
#define DP 128           // d_path
#define NE 1600000       // n_edge
#define PROJ_COLS 640    // (LP-1) * DP

// Scratch: projected features in FP16 (64 MB -> fully L2-resident).
// proj[node][l*128 + d] = sum_c W[d, l*64+c] * feat[node, c];  row NN = zero pad.
__device__ __half g_proj[(size_t)(NN + 1) * PROJ_COLS];

// Index dtype flag: 1 if paths/edge_ids are int64, 0 if int32.
__device__ int g_is64;

#define FMA_F32X2(d, a, b, c) \
  asm("fma.rn.f32x2 %0, %1, %2, %3;" : "=l"(d) : "l"(a), "l"(b), "l"(c))

// ---------------------------------------------------------------------------
// Dtype sniff (one warp): int64 index data with values in [0,50001) has all-
// zero high words; int32 randint data essentially never has 32 zero odd words.
// ---------------------------------------------------------------------------
__global__ void detect_dtype(const unsigned int* __restrict__ paths_raw) {
  unsigned v = paths_raw[threadIdx.x * 2 + 1];
  unsigned any = __ballot_sync(0xFFFFFFFFu, v != 0u);
  if (threadIdx.x == 0) g_is64 = (any == 0u) ? 1 : 0;
}

// ---------------------------------------------------------------------------
// Phase 1: proj = feat @ W^T (per-l blocks).  M=50001, N=640, K=64.
// 256 threads, 64x64 tile, 4x4 per-thread outputs, packed f32x2 FMA,
// epilogue converts to fp16.
// ---------------------------------------------------------------------------
__global__ void __launch_bounds__(256, 2) phase1_proj(
    const float* __restrict__ feat, const float* __restrict__ W) {
  __shared__ float As[64 * 68];   // [m][k], stride 68 floats
  __shared__ float Bs[64 * 64];   // [d][k], XOR-swizzled 16B chunks

  const int t = threadIdx.x;
  const int node0 = blockIdx.x * 64;
  const int cb = blockIdx.y;       // 0..9
  const int l = cb >> 1;           // path position 0..4
  const int dbase = (cb & 1) * 64;

  {
    const int c4 = (t & 15) * 4;
    const int rbase = t >> 4;
#pragma unroll
    for (int r = 0; r < 4; r++) {
      int m = rbase + r * 16;
      int node = node0 + m;
      float4 v = make_float4(0.f, 0.f, 0.f, 0.f);
      if (node < NN)
        v = *(const float4*)(feat + (size_t)node * DN + c4);
      *(float4*)(As + m * 68 + c4) = v;
    }
    const int c4i = t & 15;
#pragma unroll
    for (int r = 0; r < 4; r++) {
      int dl = rbase + r * 16;
      float4 v = *(const float4*)(W + (size_t)(dbase + dl) * 320 + l * 64 + c4i * 4);
      int sw = c4i ^ (dl >> 2);
      *(float4*)(Bs + dl * 64 + sw * 4) = v;
    }
  }
  __syncthreads();

  const int tx = t & 15;
  const int ty = t >> 4;

  unsigned long long acc0[4][4], acc1[4][4];
#pragma unroll
  for (int i = 0; i < 4; i++)
#pragma unroll
    for (int j = 0; j < 4; j++) { acc0[i][j] = 0ull; acc1[i][j] = 0ull; }

#pragma unroll
  for (int kc = 0; kc < 16; kc++) {
    ulonglong2 a[4], b[4];
#pragma unroll
    for (int mi = 0; mi < 4; mi++)
      a[mi] = *(const ulonglong2*)(As + (ty * 4 + mi) * 68 + kc * 4);
#pragma unroll
    for (int ni = 0; ni < 4; ni++) {
      int dl = tx * 4 + ni;
      int sw = kc ^ tx;
      b[ni] = *(const ulonglong2*)(Bs + dl * 64 + sw * 4);
    }
#pragma unroll
    for (int mi = 0; mi < 4; mi++)
#pragma unroll
      for (int ni = 0; ni < 4; ni++) {
        FMA_F32X2(acc0[mi][ni], a[mi].x, b[ni].x, acc0[mi][ni]);
        FMA_F32X2(acc1[mi][ni], a[mi].y, b[ni].y, acc1[mi][ni]);
      }
  }

#pragma unroll
  for (int mi = 0; mi < 4; mi++) {
    int node = node0 + ty * 4 + mi;
    if (node <= NN) {
      float o[4];
#pragma unroll
      for (int ni = 0; ni < 4; ni++) {
        unsigned lo0, hi0, lo1, hi1;
        asm("mov.b64 {%0,%1}, %2;" : "=r"(lo0), "=r"(hi0) : "l"(acc0[mi][ni]));
        asm("mov.b64 {%0,%1}, %2;" : "=r"(lo1), "=r"(hi1) : "l"(acc1[mi][ni]));
        o[ni] = (__uint_as_float(lo0) + __uint_as_float(hi0)) +
                (__uint_as_float(lo1) + __uint_as_float(hi1));
      }
      __half2 h01 = __floats2half2_rn(o[0], o[1]);
      __half2 h23 = __floats2half2_rn(o[2], o[3]);
      uint2 pk;
      pk.x = *(const unsigned*)&h01;
      pk.y = *(const unsigned*)&h23;
      *(uint2*)(g_proj + (size_t)node * PROJ_COLS + l * DP + dbase + tx * 4) = pk;
    }
  }
}

// ---------------------------------------------------------------------------
// Phase 2: one warp per (n,k). Gather 10 fp16 proj vectors (8B/lane each),
// accumulate in fp32, write 128 fp32 outputs.
// ---------------------------------------------------------------------------
__global__ void __launch_bounds__(256) phase2_gather(
    const void* __restrict__ paths_v,
    const void* __restrict__ eids_v,
    const float* __restrict__ weight,
    float* __restrict__ out) {
  const long long gw = (((long long)blockIdx.x * blockDim.x) + threadIdx.x) >> 5;
  const int lane = threadIdx.x & 31;
  if (gw >= (long long)NN * KP) return;

  const int is64 = g_is64;

  long long idx[LP];
  float w[LP - 1];
  if (is64) {
    const long long* p = (const long long*)paths_v + gw * LP;
    const long long* e = (const long long*)eids_v + gw * (LP - 1);
#pragma unroll
    for (int i = 0; i < LP; i++) {
      long long v = p[i];
      idx[i] = v < 0 ? 0 : (v > NN ? NN : v);
    }
#pragma unroll
    for (int i = 0; i < LP - 1; i++) {
      long long ev = e[i];
      ev = ev < 0 ? 0 : (ev > NE - 1 ? NE - 1 : ev);
      w[i] = weight[ev];
    }
  } else {
    const int* p = (const int*)paths_v + gw * LP;
    const int* e = (const int*)eids_v + gw * (LP - 1);
#pragma unroll
    for (int i = 0; i < LP; i++) {
      int v = p[i];
      idx[i] = v < 0 ? 0 : (v > NN ? NN : v);
    }
#pragma unroll
    for (int i = 0; i < LP - 1; i++) {
      int ev = e[i];
      ev = ev < 0 ? 0 : (ev > NE - 1 ? NE - 1 : ev);
      w[i] = weight[ev];
    }
  }

  const int col = lane * 4;   // 4 halves per lane -> 8B load per vector
  uint2 ra[LP - 1], rb[LP - 1];
#pragma unroll
  for (int i = 0; i < LP - 1; i++) {
    ra[i] = *(const uint2*)(g_proj + (size_t)idx[i] * PROJ_COLS + i * DP + col);
    rb[i] = *(const uint2*)(g_proj + (size_t)idx[i + 1] * PROJ_COLS + i * DP + col);
  }

  float4 acc = make_float4(0.f, 0.f, 0.f, 0.f);
#pragma unroll
  for (int i = 0; i < LP - 1; i++) {
    float2 a01 = __half22float2(*(const __half2*)&ra[i].x);
    float2 a23 = __half22float2(*(const __half2*)&ra[i].y);
    float2 b01 = __half22float2(*(const __half2*)&rb[i].x);
    float2 b23 = __half22float2(*(const __half2*)&rb[i].y);
    acc.x += a01.x + w[i] * b01.x;
    acc.y += a01.y + w[i] * b01.y;
    acc.z += a23.x + w[i] * b23.x;
    acc.w += a23.y + w[i] * b23.y;
  }
  *(float4*)(out + gw * DP + col) = acc;
}

// ---------------------------------------------------------------------------
// Launch. Inputs identified BY ELEMENT COUNT (all five distinct):
//   feat=3,200,000 f32 | weight=1,600,000 f32 | W=40,960 f32
//   paths=2,400,000 (i32/i64) | edge_ids=2,000,000 (i32/i64)
// ---------------------------------------------------------------------------
extern "C" void kernel_launch(void* const* d_in, const int* in_sizes, int n_in,
                              void* d_out, int out_size) {
  const float* feat = 0;
  const float* weight = 0;
  const float* W = 0;
  const void* paths = 0;
  const void* eids = 0;

  for (int i = 0; i < n_in; i++) {
    switch (in_sizes[i]) {
      case 3200000: feat   = (const float*)d_in[i]; break;
      case 1600000: weight = (const float*)d_in[i]; break;
      case 40960:   W      = (const float*)d_in[i]; break;
      case 2400000: paths  = d_in[i];               break;
      case 2000000: eids   = d_in[i];               break;
      default: break;
    }
  }
  if (!feat || !weight || !W || !paths || !eids) return;

  float* out = (float*)d_out;

  detect_dtype<<<1, 32>>>((const unsigned int*)paths);

  dim3 g1((NN + 1 + 63) / 64, 10);
  phase1_proj<<<g1, 256>>>(feat, W);

  long long warps = (long long)NN * KP;               // 400,000
  int blocks = (int)((warps * 32 + 255) / 256);       // 50,000
  phase2_gather<<<blocks, 256>>>(paths, eids, weight, out);
}